// round 16
// baseline (speedup 1.0000x reference)
#include <cuda_runtime.h>
#include <cuda_bf16.h>
#include <math.h>
#include <stdint.h>

#define BB 8
#define NN 2048
#define FF 64
#define SPLIT 2

typedef unsigned long long u64;
typedef unsigned int u32;

// -------------------- device scratch --------------------
__device__ __align__(16) float2 g_eA[BB * NN];   // (e^f1, e^{0.2f1}) * 2^-6
__device__ __align__(16) float2 g_eB[BB * NN];   // (e^f2, e^{0.2f2})
__device__ __align__(16) u32 g_hTh[BB * FF * (NN / 2)];   // H^T fp16 plane
__device__ __align__(16) uint4 g_mask[BB * NN * 16];      // interleaved ballot
__device__ __align__(16) float g_pd[SPLIT * BB * NN * FF]; // partial numerators
__device__ __align__(16) float g_pS[SPLIT * BB * NN];      // partial denominators

// -------------------- PTX helpers --------------------
#define FMA2(d, a, b, c) \
    asm("fma.rn.f32x2 %0,%1,%2,%3;" : "=l"(d) : "l"(a), "l"(b), "l"(c))
#define MUL2(d, a, b) \
    asm("mul.rn.f32x2 %0,%1,%2;" : "=l"(d) : "l"(a), "l"(b))
#define UNPACK2(lo, hi, s) \
    asm("mov.b64 {%0,%1},%2;" : "=f"(lo), "=f"(hi) : "l"(s))
#define PACKF2(d, lo, hi) \
    asm("mov.b64 %0,{%1,%2};" : "=l"(d) : "f"(lo), "f"(hi))

__device__ __forceinline__ float ex2(float x) {
    float r; asm("ex2.approx.ftz.f32 %0,%1;" : "=f"(r) : "f"(x)); return r;
}
__device__ __forceinline__ u32 smem_u32(const void* p) {
    u32 a;
    asm("{.reg .u64 t; cvta.to.shared.u64 t, %1; cvt.u32.u64 %0, t;}"
        : "=r"(a) : "l"(p));
    return a;
}

#define CPASYNC16(saddr, gptr) \
    asm volatile("cp.async.ca.shared.global [%0], [%1], 16;" \
                 :: "r"(saddr), "l"(gptr) : "memory")
#define CPCOMMIT() asm volatile("cp.async.commit_group;" ::: "memory")
#define CPWAIT0()  asm volatile("cp.async.wait_group 0;" ::: "memory")
#define CPWAIT1()  asm volatile("cp.async.wait_group 1;" ::: "memory")

#define LDSM4(r0, r1, r2, r3, addr) \
    asm volatile("ldmatrix.sync.aligned.m8n8.x4.shared.b16 {%0,%1,%2,%3}, [%4];" \
                 : "=r"(r0), "=r"(r1), "=r"(r2), "=r"(r3) : "r"(addr))

#define MMAH16816(d, a, b0, b1) \
    asm volatile("mma.sync.aligned.m16n8k16.row.col.f32.f16.f16.f32 " \
                 "{%0,%1,%2,%3}, {%4,%5,%6,%7}, {%8,%9}, {%0,%1,%2,%3};" \
                 : "+f"((d)[0]), "+f"((d)[1]), "+f"((d)[2]), "+f"((d)[3]) \
                 : "r"((a)[0]), "r"((a)[1]), "r"((a)[2]), "r"((a)[3]), \
                   "r"(b0), "r"(b1))

#define PACKH2(d, a, b) \
    asm("cvt.rn.f16x2.f32 %0,%1,%2;" : "=r"(d) : "f"(b), "f"(a))

// ---------------------------------------------------------------------------
// Kernel 1 (validated R15): blocks [0,128): GEMM + exp factors + H^T fp16;
// blocks [128,384): adj -> ballot bitmask.
// ---------------------------------------------------------------------------
#define PR2 130
#define KHF_SMEM (FF * FF * 4 + FF * PR2 * 8)

__global__ void __launch_bounds__(512) k_hf(const float* __restrict__ inp,
                                            const float* __restrict__ W,
                                            const float* __restrict__ a,
                                            const int* __restrict__ adj) {
    const int t = threadIdx.x;
    const float L2E = 1.44269504089f;

    if (blockIdx.x >= 128) {
        const int gw = (blockIdx.x - 128) * 16 + (t >> 5);
        const int lane = t & 31;
        const int4* src = (const int4*)adj + (size_t)gw * 64 * 32 + lane;
        uint4* dst = g_mask + (size_t)gw * 64;
#pragma unroll 1
        for (int r = 0; r < 8; ++r) {
            int4 v[8];
#pragma unroll
            for (int s = 0; s < 8; ++s) v[s] = src[(r * 8 + s) * 32];
#pragma unroll
            for (int s = 0; s < 8; ++s) {
                uint4 m;
                m.x = __ballot_sync(0xffffffffu, v[s].x > 0);
                m.y = __ballot_sync(0xffffffffu, v[s].y > 0);
                m.z = __ballot_sync(0xffffffffu, v[s].z > 0);
                m.w = __ballot_sync(0xffffffffu, v[s].w > 0);
                if (lane == 0) dst[r * 8 + s] = m;
            }
        }
        return;
    }

    extern __shared__ char smem[];
    float*  Ws   = (float*)smem;
    float2* IsT2 = (float2*)(smem + FF * FF * 4);

    const int row0 = blockIdx.x * 128;
    const int tx   = t & 7;
    const int ty   = t >> 3;

    ((float4*)Ws)[t]       = ((const float4*)W)[t];
    ((float4*)Ws)[t + 512] = ((const float4*)W)[t + 512];
#pragma unroll
    for (int q = 0; q < 4; ++q) {
        int idx = t + 512 * q;
        int r = idx >> 4, k4 = (idx & 15) * 4;
        float4 v = ((const float4*)(inp + (size_t)(row0 + r) * FF))[idx & 15];
        IsT2[(k4 + 0) * PR2 + r] = make_float2(v.x, v.x);
        IsT2[(k4 + 1) * PR2 + r] = make_float2(v.y, v.y);
        IsT2[(k4 + 2) * PR2 + r] = make_float2(v.z, v.z);
        IsT2[(k4 + 3) * PR2 + r] = make_float2(v.w, v.w);
    }
    __syncthreads();

    u64 acc[2][4] = {};
#pragma unroll 8
    for (int k = 0; k < FF; ++k) {
        ulonglong2 pp = *(const ulonglong2*)&IsT2[k * PR2 + ty * 2];
        u64 pd[2] = {pp.x, pp.y};
        ulonglong2 h0 = *(const ulonglong2*)&Ws[k * FF + tx * 8];
        ulonglong2 h1 = *(const ulonglong2*)&Ws[k * FF + tx * 8 + 4];
        u64 hp[4] = {h0.x, h0.y, h1.x, h1.y};
#pragma unroll
        for (int r = 0; r < 2; ++r)
#pragma unroll
            for (int c = 0; c < 4; ++c) FMA2(acc[r][c], pd[r], hp[c], acc[r][c]);
    }

    float hv[2][8];
#pragma unroll
    for (int r = 0; r < 2; ++r)
#pragma unroll
        for (int c = 0; c < 4; ++c)
            UNPACK2(hv[r][2 * c], hv[r][2 * c + 1], acc[r][c]);

    float av1[8], av2[8];
#pragma unroll
    for (int c = 0; c < 8; ++c) {
        av1[c] = __ldg(a + tx * 8 + c);
        av2[c] = __ldg(a + 64 + tx * 8 + c);
    }
#pragma unroll
    for (int r = 0; r < 2; ++r) {
        float s1 = 0.f, s2 = 0.f;
#pragma unroll
        for (int c = 0; c < 8; ++c) { s1 += hv[r][c] * av1[c]; s2 += hv[r][c] * av2[c]; }
#pragma unroll
        for (int o = 1; o < 8; o <<= 1) {
            s1 += __shfl_xor_sync(0xffffffffu, s1, o);
            s2 += __shfl_xor_sync(0xffffffffu, s2, o);
        }
        if (tx == 0) {
            const int row = row0 + ty * 2 + r;
            const float t1 = s1 * L2E, t2 = s2 * L2E;
            g_eA[row] = make_float2(ex2(t1 - 6.0f), ex2(0.2f * t1 - 6.0f));
            g_eB[row] = make_float2(ex2(t2), ex2(0.2f * t2));
        }
    }

    __syncthreads();
    u32* trH = (u32*)(smem + 16384);
#pragma unroll
    for (int c = 0; c < 8; ++c) {
        const int n = tx * 8 + c;
        u32 hi;
        PACKH2(hi, hv[0][c], hv[1][c]);
        trH[n * 68 + ty] = hi;
    }
    __syncthreads();

    const int b     = row0 >> 11;
    const int jloc0 = row0 & 2047;
    float4* dH = (float4*)g_hTh;
    {
        const int n0 = t >> 4, c0 = t & 15;
        dH[(b * 64 + n0) * 256 + (jloc0 >> 3) + c0] =
            *(const float4*)(trH + n0 * 68 + c0 * 4);
        const int idx1 = t + 512;
        const int n1 = idx1 >> 4, c1 = idx1 & 15;
        dH[(b * 64 + n1) * 256 + (jloc0 >> 3) + c1] =
            *(const float4*)(trH + n1 * 68 + c1 * 4);
    }
}

// ---------------------------------------------------------------------------
// Kernel 2: split-j attention, partial outputs. grid (SPLIT, 32, 8) = 512 CTAs
// x 256 threads, 3 CTAs/SM. Each CTA: 64 i-rows, 8 j-tiles. Inner score/MMA
// identical to R15 (validated).
// smem: [HT0 0:17408][HT1 17408:34816][MSK 34816:43008][EB 43008:51200][SP]
// ---------------------------------------------------------------------------
#define PSTRIDE 272
#define HT_STG  17408
#define SM_MSK  34816
#define SM_EB   43008
#define SM_SP   51200
#define ATTN_SMEM 51456

__global__ void __launch_bounds__(256, 3) k_attn() {
    extern __shared__ char smem[];
    const u32 sb = smem_u32(smem);
    const int t = threadIdx.x;
    const int w = t >> 5, lane = t & 31;
    const int sp = blockIdx.x;           // j-split
    const int i0 = blockIdx.y * 64;
    const int b  = blockIdx.z;
    const int mq = w & 3;
    const int kh = w >> 2;

    uint4* msk_s = (uint4*)(smem + SM_MSK);                    // [row][8]
    const ulonglong2* ebs = (const ulonglong2*)(smem + SM_EB); // 1024 local j

    const float4* hsH = (const float4*)g_hTh + (size_t)b * 64 * 256;
    const int stg_n = t >> 4, stg_c = t & 15;
    const int tt0 = sp * 8;              // first global tile of this split

    // ---- prologue: local masks (8KB) + local eB (8KB) + HT(tt0) ----
    {
        const uint4* gm = g_mask + (size_t)(b * NN + i0) * 16 + sp * 8;
#pragma unroll
        for (int u = 0; u < 2; ++u) {
            const int idx = t + 256 * u;                // 512 words
            msk_s[idx] = gm[(idx >> 3) * 16 + (idx & 7)];
        }
        const float4* ebg = (const float4*)(g_eB + (size_t)b * NN) + sp * 512;
#pragma unroll
        for (int u = 0; u < 2; ++u)
            ((float4*)(smem + SM_EB))[t + 256 * u] = ebg[t + 256 * u];
        const int n = stg_n, g = (n << 8) + (tt0 << 4) + stg_c;
        const u32 so = (u32)(n * PSTRIDE + stg_c * 16);
        CPASYNC16(sb + so, hsH + g);
        CPASYNC16(sb + so + 16 * PSTRIDE, hsH + g + (16 << 8));
        CPASYNC16(sb + so + 32 * PSTRIDE, hsH + g + (32 << 8));
        CPASYNC16(sb + so + 48 * PSTRIDE, hsH + g + (48 << 8));
        CPCOMMIT();
    }

    const int tig  = lane & 3;
    const int rloc = mq * 16 + (lane >> 2);
    u64 eA0d, eA1d;
    {
        const float2 e0 = __ldg(&g_eA[b * NN + i0 + rloc]);
        const float2 e1 = __ldg(&g_eA[b * NN + i0 + rloc + 8]);
        PACKF2(eA0d, e0.x, e0.y);
        PACKF2(eA1d, e1.x, e1.y);
    }
    float Sacc0 = 0.f, Sacc1 = 0.f;

    const u32 rowsel = (u32)(lane & 15);
    const u32 colsel = (u32)((lane >> 4) * 16);
    const u32 aBbase = sb + rowsel * PSTRIDE + colsel + (u32)kh * 128;
    const u32 bbase  = (u32)(kh * 16 + (tig >> 1));

    float d[8][4] = {};

    __syncthreads();   // masks/eB visible

    for (int ttl = 0; ttl < 8; ++ttl) {
        const u32 stoff = (u32)((ttl & 1) * HT_STG);

        if (ttl < 7) {
            const u32 stoffN = (u32)(((ttl + 1) & 1) * HT_STG);
            const int n = stg_n, g = (n << 8) + ((tt0 + ttl + 1) << 4) + stg_c;
            const u32 so = stoffN + (u32)(n * PSTRIDE + stg_c * 16);
            CPASYNC16(sb + so, hsH + g);
            CPASYNC16(sb + so + 16 * PSTRIDE, hsH + g + (16 << 8));
            CPASYNC16(sb + so + 32 * PSTRIDE, hsH + g + (32 << 8));
            CPASYNC16(sb + so + 48 * PSTRIDE, hsH + g + (48 << 8));
            CPCOMMIT();
        }

        // ---- scores -> fp16 A fragments ----
        const uint4 mr0 = msk_s[rloc * 8 + ttl];
        const uint4 mr1 = msk_s[(rloc + 8) * 8 + ttl];
        const u32 We0 = (tig & 1) ? mr0.z : mr0.x;
        const u32 Wo0 = (tig & 1) ? mr0.w : mr0.y;
        const u32 We1 = (tig & 1) ? mr1.z : mr1.x;
        const u32 Wo1 = (tig & 1) ? mr1.w : mr1.y;

        u32 AH[4][4];
#pragma unroll
        for (int kk = 0; kk < 4; ++kk) {
            const int idx = ttl * 64 + kh * 32 + kk * 8 + tig;
            const ulonglong2 e0 = ebs[idx];
            const ulonglong2 e1 = ebs[idx + 4];
            const u32 b0 = bbase + (u32)(kk * 4);

            u64 m00, m01, m02, m03, m10, m11, m12, m13;
            MUL2(m00, eA0d, e0.x); MUL2(m01, eA0d, e0.y);
            MUL2(m02, eA0d, e1.x); MUL2(m03, eA0d, e1.y);
            MUL2(m10, eA1d, e0.x); MUL2(m11, eA1d, e0.y);
            MUL2(m12, eA1d, e1.x); MUL2(m13, eA1d, e1.y);

            float x, y, p00, p01, p02, p03, p10, p11, p12, p13;
            UNPACK2(x, y, m00); p00 = ((We0 >> b0) & 1u)       ? fmaxf(x, y) : 0.f;
            UNPACK2(x, y, m01); p01 = ((Wo0 >> b0) & 1u)       ? fmaxf(x, y) : 0.f;
            UNPACK2(x, y, m02); p02 = ((We0 >> (b0 + 2)) & 1u) ? fmaxf(x, y) : 0.f;
            UNPACK2(x, y, m03); p03 = ((Wo0 >> (b0 + 2)) & 1u) ? fmaxf(x, y) : 0.f;
            UNPACK2(x, y, m10); p10 = ((We1 >> b0) & 1u)       ? fmaxf(x, y) : 0.f;
            UNPACK2(x, y, m11); p11 = ((Wo1 >> b0) & 1u)       ? fmaxf(x, y) : 0.f;
            UNPACK2(x, y, m12); p12 = ((We1 >> (b0 + 2)) & 1u) ? fmaxf(x, y) : 0.f;
            UNPACK2(x, y, m13); p13 = ((Wo1 >> (b0 + 2)) & 1u) ? fmaxf(x, y) : 0.f;

            Sacc0 += (p00 + p01) + (p02 + p03);
            Sacc1 += (p10 + p11) + (p12 + p13);
            PACKH2(AH[kk][0], p00, p01);
            PACKH2(AH[kk][1], p10, p11);
            PACKH2(AH[kk][2], p02, p03);
            PACKH2(AH[kk][3], p12, p13);
        }

        if (ttl < 7) { CPWAIT1(); } else { CPWAIT0(); }
        __syncthreads();

        // ---- MMA: m16 x n64 x k64 (this warp's k-half) ----
#pragma unroll
        for (int kk = 0; kk < 4; ++kk) {
            const u32 koff = stoff + (u32)(kk * 32);
#pragma unroll
            for (int nq = 0; nq < 4; ++nq) {
                const u32 aB = aBbase + (u32)(nq * 16 * PSTRIDE) + koff;
                u32 bh[4];
                LDSM4(bh[0], bh[1], bh[2], bh[3], aB);
                MMAH16816(d[2 * nq],     AH[kk], bh[0], bh[2]);
                MMAH16816(d[2 * nq + 1], AH[kk], bh[1], bh[3]);
            }
        }
        __syncthreads();
    }

    // ---- reduce warp pairs (kh=1 -> kh=0), write partials ----
    float* Sp = (float*)(smem + SM_SP);
    Sacc0 += __shfl_xor_sync(0xffffffffu, Sacc0, 1);
    Sacc0 += __shfl_xor_sync(0xffffffffu, Sacc0, 2);
    Sacc1 += __shfl_xor_sync(0xffffffffu, Sacc1, 1);
    Sacc1 += __shfl_xor_sync(0xffffffffu, Sacc1, 2);

    float4* Dred = (float4*)smem;
    if (kh == 1) {
        const int base = (mq * 32 + lane) * 8;
#pragma unroll
        for (int nb = 0; nb < 8; ++nb)
            Dred[base + nb] = make_float4(d[nb][0], d[nb][1], d[nb][2], d[nb][3]);
        if ((lane & 3) == 0) {
            Sp[rloc] = Sacc0;
            Sp[rloc + 8] = Sacc1;
        }
    }
    __syncthreads();

    if (kh == 0) {
        const int base = (mq * 32 + lane) * 8;
        float* pd = g_pd + (size_t)sp * BB * NN * FF;
        float* o0 = pd + ((size_t)(b * NN + i0 + rloc)) * FF + tig * 2;
        float* o1 = pd + ((size_t)(b * NN + i0 + rloc + 8)) * FF + tig * 2;
#pragma unroll
        for (int nb = 0; nb < 8; ++nb) {
            const float4 v = Dred[base + nb];
            *(float2*)(o0 + nb * 8) = make_float2(d[nb][0] + v.x, d[nb][1] + v.y);
            *(float2*)(o1 + nb * 8) = make_float2(d[nb][2] + v.z, d[nb][3] + v.w);
        }
        if ((lane & 3) == 0) {
            g_pS[(size_t)sp * BB * NN + b * NN + i0 + rloc]     = Sacc0 + Sp[rloc];
            g_pS[(size_t)sp * BB * NN + b * NN + i0 + rloc + 8] = Sacc1 + Sp[rloc + 8];
        }
    }
}

// ---------------------------------------------------------------------------
// Kernel 3: combine partials, normalize, ELU. 1024 CTAs x 256.
// ---------------------------------------------------------------------------
__global__ void __launch_bounds__(256) k_fin(float* __restrict__ out) {
    const int idx = blockIdx.x * 256 + threadIdx.x;   // 262144 float4
    const int row = idx >> 4;
    const float inv = 1.0f / (g_pS[row] + g_pS[BB * NN + row]);
    const float4 x0 = ((const float4*)g_pd)[idx];
    const float4 x1 = ((const float4*)g_pd)[idx + BB * NN * FF / 4];
    float v[4] = {(x0.x + x1.x) * inv, (x0.y + x1.y) * inv,
                  (x0.z + x1.z) * inv, (x0.w + x1.w) * inv};
#pragma unroll
    for (int c = 0; c < 4; ++c) v[c] = v[c] > 0.f ? v[c] : expm1f(v[c]);
    ((float4*)out)[idx] = make_float4(v[0], v[1], v[2], v[3]);
}

// ---------------------------------------------------------------------------
extern "C" void kernel_launch(void* const* d_in, const int* in_sizes, int n_in,
                              void* d_out, int out_size) {
    const float* inp = (const float*)d_in[0];
    const int*   adj = (const int*)d_in[1];
    const float* W   = (const float*)d_in[2];
    const float* a   = (const float*)d_in[3];
    float* out = (float*)d_out;

    cudaFuncSetAttribute(k_hf, cudaFuncAttributeMaxDynamicSharedMemorySize, KHF_SMEM);
    cudaFuncSetAttribute(k_attn, cudaFuncAttributeMaxDynamicSharedMemorySize, ATTN_SMEM);

    k_hf<<<128 + 256, 512, KHF_SMEM>>>(inp, W, a, adj);
    dim3 g(SPLIT, NN / 64, BB);
    k_attn<<<g, 256, ATTN_SMEM>>>();
    k_fin<<<(BB * NN * FF) / 4 / 256, 256>>>(out);
}